// round 10
// baseline (speedup 1.0000x reference)
#include <cuda_runtime.h>
#include <cuda_bf16.h>
#include <math.h>
#include <stdint.h>

#define BATCH 4096
#define B2    8192
#define NTILE 2080                  // triangular 128x128 tiles per branch
#define LSE_BLOCKS 128
#define PREP_BLOCKS 1024
#define GRID_P 296                  // persistent CTAs (2/SM)
#define WU 2
#define WI 3
#define WTOT (NTILE * (WU + WI))
#define LN2F 0.6931471805599453f
#define ROOT_S 2.68579135f          // sqrt(log2(e)/T) folded into operands
#define UBASE 8.0f                  // fixed user-branch basis (logits in +-7.22)

#define TROW 272
#define TILE_SM (128 * TROW)        // 34816 B
#define SMEM_REQ (3 * TILE_SM)      // A + B0 + B1 (no reduction smem needed)

__device__ __align__(256) __nv_bfloat16 g_Y[2][B2 * 128]; // [hi(64)|lo(64)]/row
// per-(rowtile, coltile, row) warp partials (m, s):
//   ct >= rt: slots 0..1 = row partials (wx) from tile (rt, ct)
//   ct <  rt: slots 0..3 = col partials (wy) from tile (ct, rt)
__device__ float2 g_p[2][64][64][128][4];   // 32 MB
__device__ float g_lse_partial[LSE_BLOCKS];
__device__ float g_pos_partial[PREP_BLOCKS];
__device__ int   g_count = 0;

// ---------------------------------------------------------------------------
__device__ __forceinline__ uint32_t smem_u32(const void* p) {
    uint32_t a;
    asm("{ .reg .u64 t; cvta.to.shared.u64 t, %1; cvt.u32.u64 %0, t; }" : "=r"(a) : "l"(p));
    return a;
}
__device__ __forceinline__ float ex2(float x) {
    float y; asm("ex2.approx.f32 %0, %1;" : "=f"(y) : "f"(x)); return y;
}
__device__ __forceinline__ float lg2(float x) {
    float y; asm("lg2.approx.f32 %0, %1;" : "=f"(y) : "f"(x)); return y;
}
__device__ __forceinline__ void ldsm4(uint32_t* r, uint32_t addr) {
    asm volatile("ldmatrix.sync.aligned.m8n8.x4.shared.b16 {%0,%1,%2,%3}, [%4];"
        : "=r"(r[0]), "=r"(r[1]), "=r"(r[2]), "=r"(r[3]) : "r"(addr));
}
__device__ __forceinline__ void mma16816(float* c, const uint32_t* a,
                                         uint32_t b0, uint32_t b1) {
    asm volatile("mma.sync.aligned.m16n8k16.row.col.f32.bf16.bf16.f32 "
        "{%0,%1,%2,%3}, {%4,%5,%6,%7}, {%8,%9}, {%0,%1,%2,%3};"
        : "+f"(c[0]), "+f"(c[1]), "+f"(c[2]), "+f"(c[3])
        : "r"(a[0]), "r"(a[1]), "r"(a[2]), "r"(a[3]), "r"(b0), "r"(b1));
}
#define CP16(dst, src) \
    asm volatile("cp.async.cg.shared.global [%0], [%1], 16;" :: "r"(dst), "l"(src))
#define CP_COMMIT() asm volatile("cp.async.commit_group;" ::: "memory")
#define CP_WAIT0()  asm volatile("cp.async.wait_group 0;" ::: "memory")

// ---------------------------------------------------------------------------
// Prep: gather, L2-normalize user branch, scale by ROOT_S, bf16 hi/lo split.
// ---------------------------------------------------------------------------
__global__ void __launch_bounds__(256) prep_kernel(
    const int* __restrict__ u_list, const int* __restrict__ i_list,
    const float* __restrict__ u1t, const float* __restrict__ i1t,
    const float* __restrict__ u2t, const float* __restrict__ i2t)
{
    int w      = blockIdx.x * 8 + (threadIdx.x >> 5);
    int lane   = threadIdx.x & 31;
    int branch = w >> 12;
    int i      = w & (BATCH - 1);

    int idx = (branch ? i_list : u_list)[i];
    const float* t1 = branch ? i1t : u1t;
    const float* t2 = branch ? i2t : u2t;

    float2 a = ((const float2*)(t1 + (size_t)idx * 64))[lane];
    float2 b = ((const float2*)(t2 + (size_t)idx * 64))[lane];

    if (branch == 0) {
        float na = a.x * a.x + a.y * a.y;
        float nb = b.x * b.x + b.y * b.y;
        #pragma unroll
        for (int o = 16; o; o >>= 1) {
            na += __shfl_xor_sync(0xffffffffu, na, o);
            nb += __shfl_xor_sync(0xffffffffu, nb, o);
        }
        float ia = rsqrtf(na), ib = rsqrtf(nb);
        a.x *= ia; a.y *= ia;
        b.x *= ib; b.y *= ib;
    }

    float pd = a.x * b.x + a.y * b.y;
    #pragma unroll
    for (int o = 16; o; o >>= 1) pd += __shfl_xor_sync(0xffffffffu, pd, o);

    __nv_bfloat16* Y = g_Y[branch];
    #pragma unroll
    for (int which = 0; which < 2; which++) {
        float2 v = which ? b : a;
        int row  = which ? (BATCH + i) : i;
        float yx = v.x * ROOT_S, yy = v.y * ROOT_S;
        __nv_bfloat16 hx = __float2bfloat16(yx);
        __nv_bfloat16 hy = __float2bfloat16(yy);
        __nv_bfloat16 lx = __float2bfloat16(yx - __bfloat162float(hx));
        __nv_bfloat16 ly = __float2bfloat16(yy - __bfloat162float(hy));
        __nv_bfloat162* rp = (__nv_bfloat162*)(Y + (size_t)row * 128);
        rp[lane]      = __nv_bfloat162(hx, hy);
        rp[32 + lane] = __nv_bfloat162(lx, ly);
    }

    __shared__ float sp_[8];
    if (lane == 0) sp_[threadIdx.x >> 5] = pd;
    __syncthreads();
    if (threadIdx.x == 0) {
        float s = 0.f;
        #pragma unroll
        for (int k = 0; k < 8; k++) s += sp_[k];
        g_pos_partial[blockIdx.x] = s;
    }
}

// ---------------------------------------------------------------------------
template<int NC16>
__device__ __forceinline__ void stage_tile(uint32_t sdst,
                                           const __nv_bfloat16* __restrict__ Y,
                                           int row0, int tid)
{
    #pragma unroll
    for (int i = 0; i < (128 * NC16) / 256; i++) {
        int l   = i * 256 + tid;
        int row = l / NC16;
        int col = l - row * NC16;
        uint32_t dst = sdst + (uint32_t)(row * TROW + col * 16);
        const char* src = (const char*)(Y + (size_t)(row0 + row) * 128) + col * 16;
        CP16(dst, src);
    }
}

// Warp tile 32m x 64n; acc[mf(2)][nf(8)][4].
template<bool FULL>
__device__ __forceinline__ void mainloop(float acc[2][8][4],
                                         uint32_t aAddr, uint32_t bAddr)
{
    #pragma unroll
    for (int kk = 0; kk < 4; kk++) {
        uint32_t ah[2][4], al[2][4];
        ldsm4(ah[0], aAddr + kk * 32);
        ldsm4(ah[1], aAddr + 16 * TROW + kk * 32);
        if (FULL) {
            ldsm4(al[0], aAddr + 128 + kk * 32);
            ldsm4(al[1], aAddr + 16 * TROW + 128 + kk * 32);
        }
        #pragma unroll
        for (int ng = 0; ng < 4; ng++) {
            uint32_t bh[4], bl[4];
            ldsm4(bh, bAddr + ng * 16 * TROW + kk * 32);
            if (FULL) ldsm4(bl, bAddr + ng * 16 * TROW + 128 + kk * 32);
            #pragma unroll
            for (int mf = 0; mf < 2; mf++) {
                mma16816(acc[mf][ng * 2],     ah[mf], bh[0], bh[1]);
                mma16816(acc[mf][ng * 2 + 1], ah[mf], bh[2], bh[3]);
                if (FULL) {
                    mma16816(acc[mf][ng * 2],     al[mf], bh[0], bh[1]);
                    mma16816(acc[mf][ng * 2 + 1], al[mf], bh[2], bh[3]);
                    mma16816(acc[mf][ng * 2],     ah[mf], bl[0], bl[1]);
                    mma16816(acc[mf][ng * 2 + 1], ah[mf], bl[2], bl[3]);
                }
            }
        }
    }
}

__device__ __forceinline__ void decode_tile(int t, int& r, int& c)
{
    r = (int)((129.0f - sqrtf(16641.0f - 8.0f * (float)t)) * 0.5f);
    while ((r + 1) * (129 - (r + 1)) / 2 <= t) r++;
    while (r * (129 - r) / 2 > t) r--;
    c = r + (t - r * (129 - r) / 2);
}

// ---------------------------------------------------------------------------
// Persistent tile kernel. Epilogue is barrier-free: each warp exports its own
// (m, s) partials directly to g_p; the exact merge happens in combine_kernel.
// ---------------------------------------------------------------------------
__global__ void __launch_bounds__(256, 2) tile_kernel()
{
    extern __shared__ unsigned char dsm[];

    int tid  = threadIdx.x;
    int lane = tid & 31;
    int wid  = tid >> 5;
    int wy   = wid >> 1;            // 0..3
    int wx   = wid & 1;             // 0..1
    int gid  = lane >> 2;
    int tig  = lane & 3;

    int k   = blockIdx.x;
    int wlo = (int)(((long long)k * WTOT) / GRID_P);
    int whi = (int)(((long long)(k + 1) * WTOT) / GRID_P);
    int u0 = (wlo + 1) >> 1, u1 = (whi + 1) >> 1;
    if (u1 > NTILE) u1 = NTILE;
    if (u0 > u1) u0 = u1;
    int lo = wlo - NTILE * WU; if (lo < 0) lo = 0;
    int hi = whi - NTILE * WU; if (hi < 0) hi = 0;
    int i0 = (lo + 2) / 3, i1 = (hi + 2) / 3;
    if (i1 > NTILE) i1 = NTILE;
    if (i0 > i1) i0 = i1;
    int nu = u1 - u0, ni = i1 - i0;
    int n = nu + ni;
    if (n == 0) return;

    uint32_t sAu = smem_u32(dsm);
    uint32_t sB0 = sAu + TILE_SM;
    uint32_t aAddr0 = sAu + (uint32_t)((wy * 32 + (lane & 7) + ((lane >> 3) & 1) * 8) * TROW
                                       + ((lane >> 4) & 1) * 16);
    uint32_t bOff   = (uint32_t)((wx * 64 + ((lane >> 4) & 1) * 8 + (lane & 7)) * TROW
                                 + ((lane >> 3) & 1) * 16);

    auto get_bt = [&](int j, int& b_, int& t_) {
        if (j < nu) { b_ = 0; t_ = u0 + j; }
        else        { b_ = 1; t_ = i0 + (j - nu); }
    };

    int b, t, r, c;
    get_bt(0, b, t);
    decode_tile(t, r, c);

    if (b == 0) { stage_tile<8>(sAu, g_Y[0], r * 128, tid);
                  stage_tile<8>(sB0, g_Y[0], c * 128, tid); }
    else        { stage_tile<16>(sAu, g_Y[1], r * 128, tid);
                  stage_tile<16>(sB0, g_Y[1], c * 128, tid); }
    CP_COMMIT();

    int buf = 0;
    for (int j = 0; j < n; j++) {
        int bn = 0, tn = 0, rn = 0, cn = 0;
        bool have_next = (j + 1 < n);
        if (have_next) { get_bt(j + 1, bn, tn); decode_tile(tn, rn, cn); }

        CP_WAIT0();
        __syncthreads();            // staged data visible; prev reads done

        if (have_next) {
            uint32_t sBn = sAu + TILE_SM + (uint32_t)((buf ^ 1) * TILE_SM);
            if (bn == 0) stage_tile<8>(sBn, g_Y[0], cn * 128, tid);
            else         stage_tile<16>(sBn, g_Y[1], cn * 128, tid);
            CP_COMMIT();
        }

        uint32_t bAddr = sAu + TILE_SM + (uint32_t)(buf * TILE_SM) + bOff;

        float acc[2][8][4];
        #pragma unroll
        for (int mf = 0; mf < 2; mf++)
            #pragma unroll
            for (int nf = 0; nf < 8; nf++)
                #pragma unroll
                for (int jj = 0; jj < 4; jj++) acc[mf][nf][jj] = 0.f;

        if (b == 0) mainloop<false>(acc, aAddr0, bAddr);
        else        mainloop<true >(acc, aAddr0, bAddr);

        __syncthreads();            // A/B smem reads complete

        if (have_next && (bn != b || rn != r)) {
            if (bn == 0) stage_tile<8>(sAu, g_Y[0], rn * 128, tid);
            else         stage_tile<16>(sAu, g_Y[1], rn * 128, tid);
            CP_COMMIT();
        }

        bool isdiag = (r == c);
        if (isdiag) {
            #pragma unroll
            for (int mf = 0; mf < 2; mf++)
                #pragma unroll
                for (int nf = 0; nf < 8; nf++)
                    #pragma unroll
                    for (int jj = 0; jj < 4; jj++) {
                        int rl = wy * 32 + mf * 16 + ((jj >> 1) & 1) * 8 + gid;
                        int cl = wx * 64 + nf * 8 + tig * 2 + (jj & 1);
                        if (rl == cl) acc[mf][nf][jj] = -1e30f;
                    }
        }

        // ================= barrier-free per-warp epilogue =================
        if (b == 0) {
            // user: fixed basis, one exp pass, plain adds
            #pragma unroll
            for (int mf = 0; mf < 2; mf++)
                #pragma unroll
                for (int nf = 0; nf < 8; nf++)
                    #pragma unroll
                    for (int jj = 0; jj < 4; jj++)
                        acc[mf][nf][jj] = ex2(acc[mf][nf][jj] - UBASE);

            #pragma unroll
            for (int mf = 0; mf < 2; mf++)
                #pragma unroll
                for (int h = 0; h < 2; h++) {
                    float v = 0.f;
                    #pragma unroll
                    for (int nf = 0; nf < 8; nf++)
                        v += acc[mf][nf][h * 2] + acc[mf][nf][h * 2 + 1];
                    v += __shfl_xor_sync(0xffffffffu, v, 1);
                    v += __shfl_xor_sync(0xffffffffu, v, 2);
                    if (tig == 0)
                        g_p[0][r][c][wy * 32 + mf * 16 + h * 8 + gid][wx] =
                            make_float2(UBASE, v);
                }
            if (!isdiag) {
                #pragma unroll
                for (int nf = 0; nf < 8; nf++)
                    #pragma unroll
                    for (int q = 0; q < 2; q++) {
                        float v = 0.f;
                        #pragma unroll
                        for (int mf = 0; mf < 2; mf++)
                            #pragma unroll
                            for (int h = 0; h < 2; h++)
                                v += acc[mf][nf][h * 2 + q];
                        v += __shfl_xor_sync(0xffffffffu, v, 4);
                        v += __shfl_xor_sync(0xffffffffu, v, 8);
                        v += __shfl_xor_sync(0xffffffffu, v, 16);
                        if (gid == 0)
                            g_p[0][c][r][wx * 64 + nf * 8 + tig * 2 + q][wy] =
                                make_float2(UBASE, v);
                    }
            }
        } else {
            // item: per-row / per-col exact bases, warp-local only
            #pragma unroll
            for (int mf = 0; mf < 2; mf++)
                #pragma unroll
                for (int h = 0; h < 2; h++) {
                    float mx = -1e30f;
                    #pragma unroll
                    for (int nf = 0; nf < 8; nf++)
                        mx = fmaxf(mx, fmaxf(acc[mf][nf][h * 2],
                                             acc[mf][nf][h * 2 + 1]));
                    mx = fmaxf(mx, __shfl_xor_sync(0xffffffffu, mx, 1));
                    mx = fmaxf(mx, __shfl_xor_sync(0xffffffffu, mx, 2));
                    float v = 0.f;
                    #pragma unroll
                    for (int nf = 0; nf < 8; nf++)
                        v += ex2(acc[mf][nf][h * 2] - mx)
                           + ex2(acc[mf][nf][h * 2 + 1] - mx);
                    v += __shfl_xor_sync(0xffffffffu, v, 1);
                    v += __shfl_xor_sync(0xffffffffu, v, 2);
                    if (tig == 0)
                        g_p[1][r][c][wy * 32 + mf * 16 + h * 8 + gid][wx] =
                            make_float2(mx, v);
                }
            if (!isdiag) {
                #pragma unroll
                for (int nf = 0; nf < 8; nf++)
                    #pragma unroll
                    for (int q = 0; q < 2; q++) {
                        float mx = -1e30f;
                        #pragma unroll
                        for (int mf = 0; mf < 2; mf++)
                            #pragma unroll
                            for (int h = 0; h < 2; h++)
                                mx = fmaxf(mx, acc[mf][nf][h * 2 + q]);
                        mx = fmaxf(mx, __shfl_xor_sync(0xffffffffu, mx, 4));
                        mx = fmaxf(mx, __shfl_xor_sync(0xffffffffu, mx, 8));
                        mx = fmaxf(mx, __shfl_xor_sync(0xffffffffu, mx, 16));
                        float v = 0.f;
                        #pragma unroll
                        for (int mf = 0; mf < 2; mf++)
                            #pragma unroll
                            for (int h = 0; h < 2; h++)
                                v += ex2(acc[mf][nf][h * 2 + q] - mx);
                        v += __shfl_xor_sync(0xffffffffu, v, 4);
                        v += __shfl_xor_sync(0xffffffffu, v, 8);
                        v += __shfl_xor_sync(0xffffffffu, v, 16);
                        if (gid == 0)
                            g_p[1][c][r][wx * 64 + nf * 8 + tig * 2 + q][wy] =
                                make_float2(mx, v);
                    }
            }
        }

        b = bn; t = tn; r = rn; c = cn;
        buf ^= 1;
    }
}

// ---------------------------------------------------------------------------
// Combine + fused finalize. Per row: merge warp partials exactly.
// Two-pass (max, then sum) for ILP on the item branch.
// ---------------------------------------------------------------------------
__global__ void __launch_bounds__(128) combine_kernel(float* __restrict__ out)
{
    int b   = blockIdx.x >> 6;
    int rt  = blockIdx.x & 63;
    int tid = threadIdx.x;
    __shared__ float sOut[4];
    __shared__ int sLast;

    float lse;
    if (b == 0) {
        float ssum = 0.f;
        #pragma unroll 4
        for (int ct = 0; ct < 64; ct++) {
            const float4* p = (const float4*)g_p[0][rt][ct][tid];
            float4 v0 = p[0];
            ssum += v0.y + v0.w;
            if (ct < rt) { float4 v1 = p[1]; ssum += v1.y + v1.w; }
        }
        lse = LN2F * (UBASE + lg2(ssum));
    } else {
        float mstar = -1e30f;
        #pragma unroll 4
        for (int ct = 0; ct < 64; ct++) {
            const float4* p = (const float4*)g_p[1][rt][ct][tid];
            float4 v0 = p[0];
            mstar = fmaxf(mstar, fmaxf(v0.x, v0.z));
            if (ct < rt) {
                float4 v1 = p[1];
                mstar = fmaxf(mstar, fmaxf(v1.x, v1.z));
            }
        }
        float ssum = 0.f;
        #pragma unroll 4
        for (int ct = 0; ct < 64; ct++) {
            const float4* p = (const float4*)g_p[1][rt][ct][tid];
            float4 v0 = p[0];
            ssum += v0.y * ex2(v0.x - mstar) + v0.w * ex2(v0.z - mstar);
            if (ct < rt) {
                float4 v1 = p[1];
                ssum += v1.y * ex2(v1.x - mstar) + v1.w * ex2(v1.z - mstar);
            }
        }
        lse = LN2F * (mstar + lg2(ssum));
    }

    #pragma unroll
    for (int o = 16; o; o >>= 1) lse += __shfl_xor_sync(0xffffffffu, lse, o);
    if ((tid & 31) == 0) sOut[tid >> 5] = lse;
    __syncthreads();
    if (tid == 0) {
        g_lse_partial[blockIdx.x] = sOut[0] + sOut[1] + sOut[2] + sOut[3];
        __threadfence();
        int old = atomicAdd(&g_count, 1);
        sLast = (old == LSE_BLOCKS - 1) ? 1 : 0;
    }
    __syncthreads();

    if (sLast) {
        __threadfence();
        float v = g_lse_partial[tid] * (1.0f / (float)B2);
        for (int i = tid; i < PREP_BLOCKS; i += 128)
            v -= g_pos_partial[i] * (1.0f / ((float)BATCH * 0.2f));
        #pragma unroll
        for (int o = 16; o; o >>= 1) v += __shfl_xor_sync(0xffffffffu, v, o);
        __shared__ float sF[4];
        if ((tid & 31) == 0) sF[tid >> 5] = v;
        __syncthreads();
        if (tid == 0) {
            out[0] = sF[0] + sF[1] + sF[2] + sF[3];
            g_count = 0;
        }
    }
}

extern "C" void kernel_launch(void* const* d_in, const int* in_sizes, int n_in,
                              void* d_out, int out_size)
{
    const int*   u_list = (const int*)  d_in[0];
    const int*   i_list = (const int*)  d_in[1];
    const float* u1     = (const float*)d_in[2];
    const float* i1     = (const float*)d_in[3];
    const float* u2     = (const float*)d_in[4];
    const float* i2     = (const float*)d_in[5];
    float* out = (float*)d_out;

    cudaFuncSetAttribute(tile_kernel, cudaFuncAttributeMaxDynamicSharedMemorySize,
                         SMEM_REQ);

    prep_kernel<<<PREP_BLOCKS, 256>>>(u_list, i_list, u1, i1, u2, i2);
    tile_kernel<<<GRID_P, 256, SMEM_REQ>>>();
    combine_kernel<<<LSE_BLOCKS, 128>>>(out);
}

// round 11
// speedup vs baseline: 1.3349x; 1.3349x over previous
#include <cuda_runtime.h>
#include <cuda_bf16.h>
#include <math.h>
#include <stdint.h>

#define BATCH 4096
#define B2    8192
#define NTILE 2080                  // triangular 128x128 tiles per branch
#define NTOT  (2 * NTILE)           // 4160
#define LSE_BLOCKS 128
#define PREP_BLOCKS 1024
#define GRID_P 296                  // persistent CTAs (2/SM)
#define LN2F 0.6931471805599453f
#define ROOT_S 2.68579135f          // sqrt(log2(e)/T) folded into operands
#define UBASE 8.0f                  // fixed user-branch basis (logits in +-7.22)

#define TROW 144                    // 128B row + 16B pad (conflict-free ldsm)
#define TILE_SM (128 * TROW)        // 18432 B
#define SMEM_RED 6144
#define SMEM_REQ (3 * TILE_SM + SMEM_RED)   // 61440 B

__device__ __align__(256) __nv_bfloat16 g_Y[2][B2 * 64];  // hi-only rows (128B)
__device__ float g_s[2][64][64][128];
__device__ float g_mv[2][64][64][128];
__device__ float g_lse_partial[LSE_BLOCKS];
__device__ float g_pos_partial[PREP_BLOCKS];
__device__ int   g_count = 0;

// ---------------------------------------------------------------------------
__device__ __forceinline__ uint32_t smem_u32(const void* p) {
    uint32_t a;
    asm("{ .reg .u64 t; cvta.to.shared.u64 t, %1; cvt.u32.u64 %0, t; }" : "=r"(a) : "l"(p));
    return a;
}
__device__ __forceinline__ float ex2(float x) {
    float y; asm("ex2.approx.f32 %0, %1;" : "=f"(y) : "f"(x)); return y;
}
__device__ __forceinline__ float lg2(float x) {
    float y; asm("lg2.approx.f32 %0, %1;" : "=f"(y) : "f"(x)); return y;
}
__device__ __forceinline__ void ldsm4(uint32_t* r, uint32_t addr) {
    asm volatile("ldmatrix.sync.aligned.m8n8.x4.shared.b16 {%0,%1,%2,%3}, [%4];"
        : "=r"(r[0]), "=r"(r[1]), "=r"(r[2]), "=r"(r[3]) : "r"(addr));
}
__device__ __forceinline__ void mma16816(float* c, const uint32_t* a,
                                         uint32_t b0, uint32_t b1) {
    asm volatile("mma.sync.aligned.m16n8k16.row.col.f32.bf16.bf16.f32 "
        "{%0,%1,%2,%3}, {%4,%5,%6,%7}, {%8,%9}, {%0,%1,%2,%3};"
        : "+f"(c[0]), "+f"(c[1]), "+f"(c[2]), "+f"(c[3])
        : "r"(a[0]), "r"(a[1]), "r"(a[2]), "r"(a[3]), "r"(b0), "r"(b1));
}
#define CP16(dst, src) \
    asm volatile("cp.async.cg.shared.global [%0], [%1], 16;" :: "r"(dst), "l"(src))
#define CP_COMMIT() asm volatile("cp.async.commit_group;" ::: "memory")
#define CP_WAIT0()  asm volatile("cp.async.wait_group 0;" ::: "memory")

// ---------------------------------------------------------------------------
// Prep: gather, L2-normalize user branch, scale by ROOT_S, bf16 hi only.
// Positive-pair dots stay exact fp32.
// ---------------------------------------------------------------------------
__global__ void __launch_bounds__(256) prep_kernel(
    const int* __restrict__ u_list, const int* __restrict__ i_list,
    const float* __restrict__ u1t, const float* __restrict__ i1t,
    const float* __restrict__ u2t, const float* __restrict__ i2t)
{
    int w      = blockIdx.x * 8 + (threadIdx.x >> 5);
    int lane   = threadIdx.x & 31;
    int branch = w >> 12;
    int i      = w & (BATCH - 1);

    int idx = (branch ? i_list : u_list)[i];
    const float* t1 = branch ? i1t : u1t;
    const float* t2 = branch ? i2t : u2t;

    float2 a = ((const float2*)(t1 + (size_t)idx * 64))[lane];
    float2 b = ((const float2*)(t2 + (size_t)idx * 64))[lane];

    if (branch == 0) {
        float na = a.x * a.x + a.y * a.y;
        float nb = b.x * b.x + b.y * b.y;
        #pragma unroll
        for (int o = 16; o; o >>= 1) {
            na += __shfl_xor_sync(0xffffffffu, na, o);
            nb += __shfl_xor_sync(0xffffffffu, nb, o);
        }
        float ia = rsqrtf(na), ib = rsqrtf(nb);
        a.x *= ia; a.y *= ia;
        b.x *= ib; b.y *= ib;
    }

    float pd = a.x * b.x + a.y * b.y;
    #pragma unroll
    for (int o = 16; o; o >>= 1) pd += __shfl_xor_sync(0xffffffffu, pd, o);

    __nv_bfloat16* Y = g_Y[branch];
    #pragma unroll
    for (int which = 0; which < 2; which++) {
        float2 v = which ? b : a;
        int row  = which ? (BATCH + i) : i;
        __nv_bfloat16 hx = __float2bfloat16(v.x * ROOT_S);
        __nv_bfloat16 hy = __float2bfloat16(v.y * ROOT_S);
        ((__nv_bfloat162*)(Y + (size_t)row * 64))[lane] = __nv_bfloat162(hx, hy);
    }

    __shared__ float sp_[8];
    if (lane == 0) sp_[threadIdx.x >> 5] = pd;
    __syncthreads();
    if (threadIdx.x == 0) {
        float s = 0.f;
        #pragma unroll
        for (int k = 0; k < 8; k++) s += sp_[k];
        g_pos_partial[blockIdx.x] = s;
    }
}

// ---------------------------------------------------------------------------
// Stage 128 rows x 128B into padded smem tile (cp.async).
// ---------------------------------------------------------------------------
__device__ __forceinline__ void stage_tile(uint32_t sdst,
                                           const __nv_bfloat16* __restrict__ Y,
                                           int row0, int tid)
{
    #pragma unroll
    for (int i = 0; i < 4; i++) {
        int l   = i * 256 + tid;
        int row = l >> 3;
        int col = l & 7;
        uint32_t dst = sdst + (uint32_t)(row * TROW + col * 16);
        const char* src = (const char*)(Y + (size_t)(row0 + row) * 64) + col * 16;
        CP16(dst, src);
    }
}

// hi*hi mainloop: warp tile 32m x 64n, acc[mf(2)][nf(8)][4].
__device__ __forceinline__ void mainloop(float acc[2][8][4],
                                         uint32_t aAddr, uint32_t bAddr)
{
    #pragma unroll
    for (int kk = 0; kk < 4; kk++) {
        uint32_t ah[2][4];
        ldsm4(ah[0], aAddr + kk * 32);
        ldsm4(ah[1], aAddr + 16 * TROW + kk * 32);
        #pragma unroll
        for (int ng = 0; ng < 4; ng++) {
            uint32_t bh[4];
            ldsm4(bh, bAddr + ng * 16 * TROW + kk * 32);
            #pragma unroll
            for (int mf = 0; mf < 2; mf++) {
                mma16816(acc[mf][ng * 2],     ah[mf], bh[0], bh[1]);
                mma16816(acc[mf][ng * 2 + 1], ah[mf], bh[2], bh[3]);
            }
        }
    }
}

__device__ __forceinline__ void decode_tile(int t, int& r, int& c)
{
    r = (int)((129.0f - sqrtf(16641.0f - 8.0f * (float)t)) * 0.5f);
    while ((r + 1) * (129 - (r + 1)) / 2 <= t) r++;
    while (r * (129 - r) / 2 > t) r--;
    c = r + (t - r * (129 - r) / 2);
}

// ---------------------------------------------------------------------------
// Persistent tile kernel: even tile split (both branches same cost now);
// A resident per row; B double-buffered via cp.async.
// ---------------------------------------------------------------------------
__global__ void __launch_bounds__(256, 2) tile_kernel()
{
    extern __shared__ unsigned char dsm[];
    float* sRowM = (float*)(dsm + 3 * TILE_SM);          // [128][2]
    float* sColM = (float*)(dsm + 3 * TILE_SM + 1024);   // [128][4]
    float* sRowS = (float*)(dsm + 3 * TILE_SM + 3072);   // [128][2]
    float* sColS = (float*)(dsm + 3 * TILE_SM + 4096);   // [128][4]

    int tid  = threadIdx.x;
    int lane = tid & 31;
    int wid  = tid >> 5;
    int wy   = wid >> 1;
    int wx   = wid & 1;
    int gid  = lane >> 2;
    int tig  = lane & 3;

    int k  = blockIdx.x;
    int t0 = (int)(((long long)k * NTOT) / GRID_P);
    int t1 = (int)(((long long)(k + 1) * NTOT) / GRID_P);
    int n  = t1 - t0;
    if (n == 0) return;

    uint32_t sAu = smem_u32(dsm);
    uint32_t sB0 = sAu + TILE_SM;
    uint32_t aAddr0 = sAu + (uint32_t)((wy * 32 + (lane & 7) + ((lane >> 3) & 1) * 8) * TROW
                                       + ((lane >> 4) & 1) * 16);
    uint32_t bOff   = (uint32_t)((wx * 64 + ((lane >> 4) & 1) * 8 + (lane & 7)) * TROW
                                 + ((lane >> 3) & 1) * 16);

    auto get_bt = [&](int j, int& b_, int& t_) {
        int g = t0 + j;
        b_ = (g >= NTILE) ? 1 : 0;
        t_ = g - b_ * NTILE;
    };

    int b, t, r, c;
    get_bt(0, b, t);
    decode_tile(t, r, c);

    stage_tile(sAu, g_Y[b], r * 128, tid);
    stage_tile(sB0, g_Y[b], c * 128, tid);
    CP_COMMIT();

    int buf = 0;
    for (int j = 0; j < n; j++) {
        int bn = 0, tn = 0, rn = 0, cn = 0;
        bool have_next = (j + 1 < n);
        if (have_next) { get_bt(j + 1, bn, tn); decode_tile(tn, rn, cn); }

        CP_WAIT0();
        __syncthreads();

        if (have_next) {
            uint32_t sBn = sAu + TILE_SM + (uint32_t)((buf ^ 1) * TILE_SM);
            stage_tile(sBn, g_Y[bn], cn * 128, tid);
            CP_COMMIT();
        }

        uint32_t bAddr = sAu + TILE_SM + (uint32_t)(buf * TILE_SM) + bOff;

        float acc[2][8][4];
        #pragma unroll
        for (int mf = 0; mf < 2; mf++)
            #pragma unroll
            for (int nf = 0; nf < 8; nf++)
                #pragma unroll
                for (int jj = 0; jj < 4; jj++) acc[mf][nf][jj] = 0.f;

        mainloop(acc, aAddr0, bAddr);

        __syncthreads();

        if (have_next && (bn != b || rn != r)) {
            stage_tile(sAu, g_Y[bn], rn * 128, tid);
            CP_COMMIT();
        }

        bool isdiag = (r == c);
        if (isdiag) {
            #pragma unroll
            for (int mf = 0; mf < 2; mf++)
                #pragma unroll
                for (int nf = 0; nf < 8; nf++)
                    #pragma unroll
                    for (int jj = 0; jj < 4; jj++) {
                        int rl = wy * 32 + mf * 16 + ((jj >> 1) & 1) * 8 + gid;
                        int cl = wx * 64 + nf * 8 + tig * 2 + (jj & 1);
                        if (rl == cl) acc[mf][nf][jj] = -1e30f;
                    }
        }

        if (b == 0) {
            // ---- user: fixed basis, one exp pass ----
            #pragma unroll
            for (int mf = 0; mf < 2; mf++)
                #pragma unroll
                for (int nf = 0; nf < 8; nf++)
                    #pragma unroll
                    for (int jj = 0; jj < 4; jj++)
                        acc[mf][nf][jj] = ex2(acc[mf][nf][jj] - UBASE);

            #pragma unroll
            for (int mf = 0; mf < 2; mf++)
                #pragma unroll
                for (int h = 0; h < 2; h++) {
                    float v = 0.f;
                    #pragma unroll
                    for (int nf = 0; nf < 8; nf++)
                        v += acc[mf][nf][h * 2] + acc[mf][nf][h * 2 + 1];
                    v += __shfl_xor_sync(0xffffffffu, v, 1);
                    v += __shfl_xor_sync(0xffffffffu, v, 2);
                    if (tig == 0)
                        sRowS[(wy * 32 + mf * 16 + h * 8 + gid) * 2 + wx] = v;
                }
            if (!isdiag) {
                #pragma unroll
                for (int nf = 0; nf < 8; nf++)
                    #pragma unroll
                    for (int q = 0; q < 2; q++) {
                        float v = 0.f;
                        #pragma unroll
                        for (int mf = 0; mf < 2; mf++)
                            #pragma unroll
                            for (int h = 0; h < 2; h++)
                                v += acc[mf][nf][h * 2 + q];
                        v += __shfl_xor_sync(0xffffffffu, v, 4);
                        v += __shfl_xor_sync(0xffffffffu, v, 8);
                        v += __shfl_xor_sync(0xffffffffu, v, 16);
                        if (gid == 0)
                            sColS[(wx * 64 + nf * 8 + tig * 2 + q) * 4 + wy] = v;
                    }
            }
            __syncthreads();
            if (tid < 128) {
                g_s[0][r][c][tid]  = sRowS[tid * 2] + sRowS[tid * 2 + 1];
                g_mv[0][r][c][tid] = UBASE;
                if (!isdiag) {
                    g_s[0][c][r][tid]  = sColS[tid * 4] + sColS[tid * 4 + 1]
                                       + sColS[tid * 4 + 2] + sColS[tid * 4 + 3];
                    g_mv[0][c][r][tid] = UBASE;
                }
            }
            __syncthreads();
        } else {
            // ---- item: exact per-row / per-col bases ----
            #pragma unroll
            for (int mf = 0; mf < 2; mf++)
                #pragma unroll
                for (int h = 0; h < 2; h++) {
                    float v = -1e30f;
                    #pragma unroll
                    for (int nf = 0; nf < 8; nf++)
                        v = fmaxf(v, fmaxf(acc[mf][nf][h * 2],
                                           acc[mf][nf][h * 2 + 1]));
                    v = fmaxf(v, __shfl_xor_sync(0xffffffffu, v, 1));
                    v = fmaxf(v, __shfl_xor_sync(0xffffffffu, v, 2));
                    if (tig == 0)
                        sRowM[(wy * 32 + mf * 16 + h * 8 + gid) * 2 + wx] = v;
                }
            #pragma unroll
            for (int nf = 0; nf < 8; nf++)
                #pragma unroll
                for (int q = 0; q < 2; q++) {
                    float v = -1e30f;
                    #pragma unroll
                    for (int mf = 0; mf < 2; mf++)
                        #pragma unroll
                        for (int h = 0; h < 2; h++)
                            v = fmaxf(v, acc[mf][nf][h * 2 + q]);
                    v = fmaxf(v, __shfl_xor_sync(0xffffffffu, v, 4));
                    v = fmaxf(v, __shfl_xor_sync(0xffffffffu, v, 8));
                    v = fmaxf(v, __shfl_xor_sync(0xffffffffu, v, 16));
                    if (gid == 0)
                        sColM[(wx * 64 + nf * 8 + tig * 2 + q) * 4 + wy] = v;
                }
            __syncthreads();

            float rm[2][2], cm[8][2];
            #pragma unroll
            for (int mf = 0; mf < 2; mf++)
                #pragma unroll
                for (int h = 0; h < 2; h++) {
                    int row = wy * 32 + mf * 16 + h * 8 + gid;
                    rm[mf][h] = fmaxf(sRowM[row * 2], sRowM[row * 2 + 1]);
                }
            #pragma unroll
            for (int nf = 0; nf < 8; nf++)
                #pragma unroll
                for (int q = 0; q < 2; q++) {
                    int col = wx * 64 + nf * 8 + tig * 2 + q;
                    cm[nf][q] = fmaxf(fmaxf(sColM[col * 4], sColM[col * 4 + 1]),
                                      fmaxf(sColM[col * 4 + 2], sColM[col * 4 + 3]));
                }

            #pragma unroll
            for (int mf = 0; mf < 2; mf++)
                #pragma unroll
                for (int h = 0; h < 2; h++) {
                    float v = 0.f, mmx = rm[mf][h];
                    #pragma unroll
                    for (int nf = 0; nf < 8; nf++)
                        v += ex2(acc[mf][nf][h * 2] - mmx)
                           + ex2(acc[mf][nf][h * 2 + 1] - mmx);
                    v += __shfl_xor_sync(0xffffffffu, v, 1);
                    v += __shfl_xor_sync(0xffffffffu, v, 2);
                    if (tig == 0)
                        sRowS[(wy * 32 + mf * 16 + h * 8 + gid) * 2 + wx] = v;
                }
            if (!isdiag) {
                #pragma unroll
                for (int nf = 0; nf < 8; nf++)
                    #pragma unroll
                    for (int q = 0; q < 2; q++) {
                        float v = 0.f, mmx = cm[nf][q];
                        #pragma unroll
                        for (int mf = 0; mf < 2; mf++)
                            #pragma unroll
                            for (int h = 0; h < 2; h++)
                                v += ex2(acc[mf][nf][h * 2 + q] - mmx);
                        v += __shfl_xor_sync(0xffffffffu, v, 4);
                        v += __shfl_xor_sync(0xffffffffu, v, 8);
                        v += __shfl_xor_sync(0xffffffffu, v, 16);
                        if (gid == 0)
                            sColS[(wx * 64 + nf * 8 + tig * 2 + q) * 4 + wy] = v;
                    }
            }
            __syncthreads();
            if (tid < 128) {
                g_s[1][r][c][tid]  = sRowS[tid * 2] + sRowS[tid * 2 + 1];
                g_mv[1][r][c][tid] = fmaxf(sRowM[tid * 2], sRowM[tid * 2 + 1]);
                if (!isdiag) {
                    g_s[1][c][r][tid]  = sColS[tid * 4] + sColS[tid * 4 + 1]
                                       + sColS[tid * 4 + 2] + sColS[tid * 4 + 3];
                    g_mv[1][c][r][tid] = fmaxf(fmaxf(sColM[tid * 4], sColM[tid * 4 + 1]),
                                               fmaxf(sColM[tid * 4 + 2], sColM[tid * 4 + 3]));
                }
            }
            __syncthreads();
        }

        b = bn; t = tn; r = rn; c = cn;
        buf ^= 1;
    }
}

// ---------------------------------------------------------------------------
// Combine + fused finalize.
// ---------------------------------------------------------------------------
__global__ void __launch_bounds__(128) combine_kernel(float* __restrict__ out)
{
    int b   = blockIdx.x >> 6;
    int rt  = blockIdx.x & 63;
    int tid = threadIdx.x;
    __shared__ float sOut[4];
    __shared__ int sLast;

    float m = -1e30f, s = 0.f;
    #pragma unroll 8
    for (int ct = 0; ct < 64; ct++) {
        float mc = g_mv[b][rt][ct][tid];
        float sc = g_s[b][rt][ct][tid];
        float mn = fmaxf(m, mc);
        s = s * ex2(m - mn) + sc * ex2(mc - mn);
        m = mn;
    }
    float lse = LN2F * (m + lg2(s));
    #pragma unroll
    for (int o = 16; o; o >>= 1) lse += __shfl_xor_sync(0xffffffffu, lse, o);
    if ((tid & 31) == 0) sOut[tid >> 5] = lse;
    __syncthreads();
    if (tid == 0) {
        g_lse_partial[blockIdx.x] = sOut[0] + sOut[1] + sOut[2] + sOut[3];
        __threadfence();
        int old = atomicAdd(&g_count, 1);
        sLast = (old == LSE_BLOCKS - 1) ? 1 : 0;
    }
    __syncthreads();

    if (sLast) {
        __threadfence();
        float v = g_lse_partial[tid] * (1.0f / (float)B2);
        for (int i = tid; i < PREP_BLOCKS; i += 128)
            v -= g_pos_partial[i] * (1.0f / ((float)BATCH * 0.2f));
        #pragma unroll
        for (int o = 16; o; o >>= 1) v += __shfl_xor_sync(0xffffffffu, v, o);
        __shared__ float sF[4];
        if ((tid & 31) == 0) sF[tid >> 5] = v;
        __syncthreads();
        if (tid == 0) {
            out[0] = sF[0] + sF[1] + sF[2] + sF[3];
            g_count = 0;
        }
    }
}

extern "C" void kernel_launch(void* const* d_in, const int* in_sizes, int n_in,
                              void* d_out, int out_size)
{
    const int*   u_list = (const int*)  d_in[0];
    const int*   i_list = (const int*)  d_in[1];
    const float* u1     = (const float*)d_in[2];
    const float* i1     = (const float*)d_in[3];
    const float* u2     = (const float*)d_in[4];
    const float* i2     = (const float*)d_in[5];
    float* out = (float*)d_out;

    cudaFuncSetAttribute(tile_kernel, cudaFuncAttributeMaxDynamicSharedMemorySize,
                         SMEM_REQ);

    prep_kernel<<<PREP_BLOCKS, 256>>>(u_list, i_list, u1, i1, u2, i2);
    tile_kernel<<<GRID_P, 256, SMEM_REQ>>>();
    combine_kernel<<<LSE_BLOCKS, 128>>>(out);
}